// round 12
// baseline (speedup 1.0000x reference)
#include <cuda_runtime.h>
#include <cuda_bf16.h>
#include <cstdint>

#define B_  2
#define LQ  1024
#define LK  2048
#define DM  1024
#define NH  16
#define DH  64
#define BH  (B_*NH)
#define OUT_ELEMS (B_*LQ*DM)

// fp32 (tf32-rounded) pools
__device__ __align__(256) float  g_Q[BH*LQ*DH];     // scaled 1/8, rounded
__device__ __align__(256) float  g_K[BH*LK*DH];     // rounded
__device__ __align__(256) float  g_Vt[BH*DH*LK];    // [bh, d, t], rounded
__device__ __align__(256) float  g_ctx[B_*LQ*DM];   // rounded
__device__ __align__(256) float2 g_pstats[BH*LQ*16];
__device__ __align__(256) float  g_scale[BH*LQ*16];

// ---------------- low-level helpers ----------------------------------------
__device__ __forceinline__ uint32_t smem_u32(const void* p){
    uint32_t a;
    asm("{ .reg .u64 t; cvta.to.shared.u64 t, %1; cvt.u32.u64 %0, t; }" : "=r"(a) : "l"(p));
    return a;
}
#define CP16(d,s) asm volatile("cp.async.cg.shared.global [%0], [%1], 16;" :: "r"(d), "l"(__cvta_generic_to_global(s)))
#define CPCOMMIT() asm volatile("cp.async.commit_group;" ::: "memory")
#define CPWAIT(n)  asm volatile("cp.async.wait_group %0;" :: "n"(n) : "memory")

__device__ __forceinline__ float tf32r(float x){
    uint32_t u; asm("cvt.rna.tf32.f32 %0, %1;" : "=r"(u) : "f"(x));
    return __uint_as_float(u);
}
__device__ __forceinline__ void mma_tf32(float* d, const float* a, const float* b){
    asm volatile("mma.sync.aligned.m16n8k8.row.col.f32.tf32.tf32.f32 "
        "{%0,%1,%2,%3}, {%4,%5,%6,%7}, {%8,%9}, {%0,%1,%2,%3};"
        : "+f"(d[0]),"+f"(d[1]),"+f"(d[2]),"+f"(d[3])
        : "r"(__float_as_uint(a[0])),"r"(__float_as_uint(a[1])),
          "r"(__float_as_uint(a[2])),"r"(__float_as_uint(a[3])),
          "r"(__float_as_uint(b[0])),"r"(__float_as_uint(b[1])));
}

// smem tile geometry: 128 rows x 64 fp32 cols, stride 68 floats (bank = lane)
#define TROW   68
#define TILEB  (128*TROW*4)     // 34816 bytes

// ============================================================================
// Projection: C[128x128] = A[M,1024] @ W[128,1024]^T + bias, tf32 MMA.
// smem: [0,512) bias | tiles A,W @512 (2*34816) | stage fp32 128x132 overlays
// mode 0: Q (scale 1/8 -> g_Q), 1: K, 2: V transposed -> g_Vt, 3: O fp32 out
// ============================================================================
#define PROJ_SMEM (512 + 2*TILEB)

__device__ __forceinline__ void proj_body(
    int mode, int m0, int n0,
    const float* __restrict__ A, const float* __restrict__ W,
    const float* __restrict__ bias, float* __restrict__ outp, int Ltok)
{
    extern __shared__ char smc[];
    float* bias_sm = (float*)smc;
    float* Sa = (float*)(smc + 512);
    float* Sw = Sa + 128*TROW;
    float* stg = (float*)(smc + 512);   // overlays tiles after final MMA

    const int tid = threadIdx.x, lane = tid&31, wid = tid>>5;
    const int wm = wid>>1, wn = wid&1;
    const int g = lane>>2, tg = lane&3;

    if (tid < 128) bias_sm[tid] = bias[n0+tid];

    float acc[2][8][4];
#pragma unroll
    for (int a=0;a<2;a++)
#pragma unroll
        for (int b=0;b<8;b++)
#pragma unroll
            for (int c=0;c<4;c++) acc[a][b][c]=0.f;

    for (int ck=0; ck<16; ck++){
        __syncthreads();
#pragma unroll
        for (int i=0;i<8;i++){
            int idx = tid + i*256;          // 2048 float4 per tile
            int row = idx>>4, c = idx&15;
            float4 v = *(const float4*)(A + (size_t)(m0+row)*DM + ck*64 + c*4);
            float4 w = *(const float4*)(W + (size_t)(n0+row)*DM + ck*64 + c*4);
            float4 rv, rw;
            rv.x=tf32r(v.x); rv.y=tf32r(v.y); rv.z=tf32r(v.z); rv.w=tf32r(v.w);
            rw.x=tf32r(w.x); rw.y=tf32r(w.y); rw.z=tf32r(w.z); rw.w=tf32r(w.w);
            *(float4*)(Sa + row*TROW + c*4) = rv;
            *(float4*)(Sw + row*TROW + c*4) = rw;
        }
        __syncthreads();
#pragma unroll
        for (int ks=0;ks<8;ks++){
            float a[2][4];
#pragma unroll
            for (int mt=0;mt<2;mt++){
                int rb = wm*32 + mt*16;
                a[mt][0] = Sa[(rb+g  )*TROW + ks*8+tg];
                a[mt][1] = Sa[(rb+g+8)*TROW + ks*8+tg];
                a[mt][2] = Sa[(rb+g  )*TROW + ks*8+tg+4];
                a[mt][3] = Sa[(rb+g+8)*TROW + ks*8+tg+4];
            }
#pragma unroll
            for (int nt=0;nt<8;nt++){
                float b[2];
                b[0] = Sw[(wn*64+nt*8+g)*TROW + ks*8+tg];
                b[1] = Sw[(wn*64+nt*8+g)*TROW + ks*8+tg+4];
                mma_tf32(acc[0][nt], a[0], b);
                mma_tf32(acc[1][nt], a[1], b);
            }
        }
    }
    __syncthreads();

    // stage accumulators (+bias, Q scale)
    {
#pragma unroll
        for (int mt=0;mt<2;mt++)
#pragma unroll
            for (int nt=0;nt<8;nt++){
                int row = wm*32 + mt*16 + g;
                int col = wn*64 + nt*8 + tg*2;
                float b0 = bias_sm[col], b1 = bias_sm[col+1];
                float v0 = acc[mt][nt][0]+b0, v1 = acc[mt][nt][1]+b1;
                float v2 = acc[mt][nt][2]+b0, v3 = acc[mt][nt][3]+b1;
                if (mode==0){ v0*=0.125f; v1*=0.125f; v2*=0.125f; v3*=0.125f; }
                stg[row*132+col] = v0;  stg[row*132+col+1] = v1;
                stg[(row+8)*132+col] = v2; stg[(row+8)*132+col+1] = v3;
            }
    }
    __syncthreads();

    if (mode==3){
        const int r2 = tid>>1, hf = tid&1;
        const float* srow = stg + r2*132 + hf*64;
        float* drow = outp + (size_t)(m0+r2)*DM + n0 + hf*64;
#pragma unroll
        for (int j=0;j<16;j++) *(float4*)(drow + j*4) = *(const float4*)(srow + j*4);
    } else if (mode<2){
        const int r2 = tid>>1, hf = tid&1;
        const int rowg = m0 + r2;
        const int b = rowg / Ltok, tok = rowg - b*Ltok;
        const int h = (n0>>6) + hf;
        const float* srow = stg + r2*132 + hf*64;
        float* dst = ((mode==0)? g_Q : g_K) + ((size_t)(b*NH+h)*Ltok + tok)*DH;
#pragma unroll
        for (int j=0;j<16;j++){
            float4 o;
            o.x=tf32r(srow[j*4+0]); o.y=tf32r(srow[j*4+1]);
            o.z=tf32r(srow[j*4+2]); o.w=tf32r(srow[j*4+3]);
            *(float4*)(dst + j*4) = o;
        }
    } else {
        const int dl = tid>>1, th = tid&1;
        const int dg = n0 + dl, h = dg>>6, dd = dg&63;
        const int b = m0 / Ltok, toff = m0 - b*Ltok;
        float* vt = g_Vt + ((size_t)(b*NH+h)*DH + dd)*LK + toff + th*64;
#pragma unroll
        for (int j=0;j<16;j++){
            int t4 = th*64 + j*4;
            float4 o;
            o.x=tf32r(stg[(t4+0)*132+dl]);
            o.y=tf32r(stg[(t4+1)*132+dl]);
            o.z=tf32r(stg[(t4+2)*132+dl]);
            o.w=tf32r(stg[(t4+3)*132+dl]);
            *(float4*)(vt + j*4) = o;
        }
    }
}

// fused Q/K/V projection: grid (8, 80): y<16 Q, y<48 K, else V
__global__ void __launch_bounds__(256,2) qkv_kernel(
    const float* __restrict__ query, const float* __restrict__ key, const float* __restrict__ value,
    const float* __restrict__ Wq, const float* __restrict__ Wk, const float* __restrict__ Wv,
    const float* __restrict__ bq, const float* __restrict__ bk, const float* __restrict__ bv)
{
    const int my = blockIdx.y, n0 = blockIdx.x*128;
    if (my < 16)
        proj_body(0, my*128, n0, query, Wq, bq, nullptr, LQ);
    else if (my < 48)
        proj_body(1, (my-16)*128, n0, key, Wk, bk, nullptr, LK);
    else
        proj_body(2, (my-48)*128, n0, value, Wv, bv, nullptr, LK);
}

__global__ void __launch_bounds__(256,2) oproj_kernel(
    const float* __restrict__ Wo, const float* __restrict__ bo, float* __restrict__ out)
{
    proj_body(3, blockIdx.y*128, blockIdx.x*128, g_ctx, Wo, bo, out, LQ);
}

// ============================================================================
// Scores: S = Q@K^T + bias, mask; writes exp(s-m_tile) to attn, per-tile
// (max,sum) -> g_pstats. Tiles via cp.async (pools pre-rounded).
// ============================================================================
#define SC_SMEM (2*TILEB)
__global__ void __launch_bounds__(256,2) scores_kernel(
    const float* __restrict__ bias, const int* __restrict__ mask,
    float* __restrict__ attn)
{
    extern __shared__ char smc[];
    const uint32_t sb = smem_u32(smc);
    float* Sq = (float*)smc;
    float* Sk = Sq + 128*TROW;
    float* stg = (float*)smc;
    const int tid = threadIdx.x, lane = tid&31, wid = tid>>5;
    const int wm = wid>>1, wn = wid&1;
    const int g = lane>>2, tg = lane&3;
    const int k0 = blockIdx.x*128, q0 = blockIdx.y*128, bh = blockIdx.z, b = bh>>4;
    const int kt = blockIdx.x;

    const float* Qg = g_Q + ((size_t)bh*LQ + q0)*DH;
    const float* Kg = g_K + ((size_t)bh*LK + k0)*DH;
#pragma unroll
    for (int i=0;i<8;i++){
        int idx = tid + i*256, row = idx>>4, c = idx&15;
        CP16(sb + row*(TROW*4) + c*16,         Qg + (size_t)row*DH + c*4);
        CP16(sb + TILEB + row*(TROW*4) + c*16, Kg + (size_t)row*DH + c*4);
    }
    CPCOMMIT(); CPWAIT(0);
    __syncthreads();

    float acc[2][8][4];
#pragma unroll
    for (int a=0;a<2;a++)
#pragma unroll
        for (int c=0;c<8;c++)
#pragma unroll
            for (int d=0;d<4;d++) acc[a][c][d]=0.f;

#pragma unroll
    for (int ks=0;ks<8;ks++){
        float a[2][4];
#pragma unroll
        for (int mt=0;mt<2;mt++){
            int rb = wm*32 + mt*16;
            a[mt][0] = Sq[(rb+g  )*TROW + ks*8+tg];
            a[mt][1] = Sq[(rb+g+8)*TROW + ks*8+tg];
            a[mt][2] = Sq[(rb+g  )*TROW + ks*8+tg+4];
            a[mt][3] = Sq[(rb+g+8)*TROW + ks*8+tg+4];
        }
#pragma unroll
        for (int nt=0;nt<8;nt++){
            float b2[2];
            b2[0] = Sk[(wn*64+nt*8+g)*TROW + ks*8+tg];
            b2[1] = Sk[(wn*64+nt*8+g)*TROW + ks*8+tg+4];
            mma_tf32(acc[0][nt], a[0], b2);
            mma_tf32(acc[1][nt], a[1], b2);
        }
    }
    __syncthreads();   // tiles dead; stage overlays
    {
#pragma unroll
        for (int mt=0;mt<2;mt++)
#pragma unroll
            for (int nt=0;nt<8;nt++){
                int row = wm*32 + mt*16 + g;
                int col = wn*64 + nt*8 + tg*2;
                stg[row*132+col] = acc[mt][nt][0];  stg[row*132+col+1] = acc[mt][nt][1];
                stg[(row+8)*132+col] = acc[mt][nt][2]; stg[(row+8)*132+col+1] = acc[mt][nt][3];
            }
    }
    __syncthreads();
    {
        const int r2 = tid>>1, hf = tid&1;
        const int q = q0 + r2;
        float* srow = stg + r2*132 + hf*64;
        const float* brow = bias + ((size_t)bh*LQ + q)*LK + k0 + hf*64;
        const int*   mrow = mask + ((size_t)b*LQ  + q)*LK + k0 + hf*64;
        float mx = -3.0e38f;
#pragma unroll
        for (int j=0;j<16;j++){
            float4 s = *(const float4*)(srow + j*4);
            float4 bb = *(const float4*)(brow + j*4);
            int4   mm = *(const int4*)  (mrow + j*4);
            s.x = mm.x ? s.x+bb.x : -1e9f;
            s.y = mm.y ? s.y+bb.y : -1e9f;
            s.z = mm.z ? s.z+bb.z : -1e9f;
            s.w = mm.w ? s.w+bb.w : -1e9f;
            mx = fmaxf(mx, fmaxf(fmaxf(s.x,s.y), fmaxf(s.z,s.w)));
            *(float4*)(srow + j*4) = s;
        }
        mx = fmaxf(mx, __shfl_xor_sync(0xffffffffu, mx, 1));
        float sum = 0.f;
        float* arow = attn + ((size_t)bh*LQ + q)*LK + k0 + hf*64;
#pragma unroll
        for (int j=0;j<16;j++){
            float4 s = *(const float4*)(srow + j*4);
            float4 e;
            e.x = __expf(s.x-mx); e.y = __expf(s.y-mx);
            e.z = __expf(s.z-mx); e.w = __expf(s.w-mx);
            sum += (e.x+e.y)+(e.z+e.w);
            *(float4*)(arow + j*4) = e;
        }
        sum += __shfl_xor_sync(0xffffffffu, sum, 1);
        if (hf == 0)
            g_pstats[((size_t)bh*LQ + q)*16 + kt] = make_float2(mx, sum);
    }
}

// ============================================================================
// Merge per-row tile partials -> per-tile normalization scales
// ============================================================================
__global__ void __launch_bounds__(256) merge_kernel()
{
    const int row = blockIdx.x*256 + threadIdx.x;
    float2 p[16];
#pragma unroll
    for (int t=0;t<16;t++) p[t] = g_pstats[(size_t)row*16 + t];
    float m = p[0].x;
#pragma unroll
    for (int t=1;t<16;t++) m = fmaxf(m, p[t].x);
    float e[16]; float S = 0.f;
#pragma unroll
    for (int t=0;t<16;t++){ e[t] = __expf(p[t].x - m); S += p[t].y * e[t]; }
    const float inv = 1.f / S;
#pragma unroll
    for (int t=0;t<16;t++) g_scale[(size_t)row*16 + t] = e[t] * inv;
}

// ============================================================================
// PV: exp * per-tile scale -> normalized probs written back + tf32 MMA.
// smem: P[128x68f] @0 (34816) | V[64x68f] @34816 (17408) | ssc @52224 (8KB)
// ============================================================================
#define PV_SMEM (TILEB + 64*TROW*4 + 8192)
__global__ void __launch_bounds__(256,2) pv_kernel(float* __restrict__ attn)
{
    extern __shared__ char smc[];
    const uint32_t sb = smem_u32(smc);
    float* Ps = (float*)smc;
    float* Vs = Ps + 128*TROW;
    float* ssc = (float*)(smc + TILEB + 64*TROW*4);
    float* stg = (float*)smc;                // overlays P tile
    const int tid = threadIdx.x, lane = tid&31, wid = tid>>5;
    const int wm = wid>>1, wn = wid&1;
    const int g = lane>>2, tg = lane&3;
    const int q0 = blockIdx.x*128, bh = blockIdx.y, b = bh>>4, h = bh&15;

    float* Pg = attn + ((size_t)bh*LQ + q0)*LK;
    const float* Vg = g_Vt + (size_t)bh*DH*LK;

#pragma unroll
    for (int i=0;i<8;i++){
        int idx = tid + i*256;
        int r = idx>>4;
        ssc[idx] = g_scale[((size_t)bh*LQ + q0 + r)*16 + (idx&15)];
    }

    float acc[2][4][4];
#pragma unroll
    for (int a=0;a<2;a++)
#pragma unroll
        for (int c=0;c<4;c++)
#pragma unroll
            for (int d=0;d<4;d++) acc[a][c][d]=0.f;

    for (int ck=0; ck<32; ck++){
        const int t0 = ck*64;
        const int kt2 = ck>>1;
        __syncthreads();
        // V tile via cp.async (pre-rounded)
#pragma unroll
        for (int i=0;i<4;i++){
            int idx = tid + i*256, row = idx>>4, c = idx&15;
            CP16(sb + TILEB + row*(TROW*4) + c*16, Vg + (size_t)row*LK + t0 + c*4);
        }
        CPCOMMIT();
        // P: normalize, write back, round into smem
#pragma unroll
        for (int i=0;i<8;i++){
            int idx = tid + i*256, row = idx>>4, c4 = idx&15;
            const float sc = ssc[row*16 + kt2];
            float* pp = Pg + (size_t)row*LK + t0 + c4*4;
            float4 v = *(const float4*)pp;
            v.x *= sc; v.y *= sc; v.z *= sc; v.w *= sc;
            *(float4*)pp = v;
            float4 r;
            r.x=tf32r(v.x); r.y=tf32r(v.y); r.z=tf32r(v.z); r.w=tf32r(v.w);
            *(float4*)(Ps + row*TROW + c4*4) = r;
        }
        CPWAIT(0);
        __syncthreads();
#pragma unroll
        for (int ks=0;ks<8;ks++){
            float a[2][4];
#pragma unroll
            for (int mt=0;mt<2;mt++){
                int rb = wm*32 + mt*16;
                a[mt][0] = Ps[(rb+g  )*TROW + ks*8+tg];
                a[mt][1] = Ps[(rb+g+8)*TROW + ks*8+tg];
                a[mt][2] = Ps[(rb+g  )*TROW + ks*8+tg+4];
                a[mt][3] = Ps[(rb+g+8)*TROW + ks*8+tg+4];
            }
#pragma unroll
            for (int nt=0;nt<4;nt++){
                float b2[2];
                b2[0] = Vs[(wn*32+nt*8+g)*TROW + ks*8+tg];
                b2[1] = Vs[(wn*32+nt*8+g)*TROW + ks*8+tg+4];
                mma_tf32(acc[0][nt], a[0], b2);
                mma_tf32(acc[1][nt], a[1], b2);
            }
        }
    }
    __syncthreads();   // P tile dead; stage overlays
    {
#pragma unroll
        for (int mt=0;mt<2;mt++)
#pragma unroll
            for (int nt=0;nt<4;nt++){
                int row = wm*32 + mt*16 + g;
                int col = wn*32 + nt*8 + tg*2;
                stg[row*TROW+col] = acc[mt][nt][0];  stg[row*TROW+col+1] = acc[mt][nt][1];
                stg[(row+8)*TROW+col] = acc[mt][nt][2]; stg[(row+8)*TROW+col+1] = acc[mt][nt][3];
            }
    }
    __syncthreads();
    {
        const int r2 = tid>>1, hf = tid&1;
        const float* srow = stg + r2*TROW + hf*32;
        float* dst = g_ctx + ((size_t)(b*LQ + q0 + r2))*DM + h*DH + hf*32;
#pragma unroll
        for (int j=0;j<8;j++){
            float4 o;
            o.x=tf32r(srow[j*4+0]); o.y=tf32r(srow[j*4+1]);
            o.z=tf32r(srow[j*4+2]); o.w=tf32r(srow[j*4+3]);
            *(float4*)(dst + j*4) = o;
        }
    }
}

// ============================================================================
extern "C" void kernel_launch(void* const* d_in, const int* in_sizes, int n_in,
                              void* d_out, int out_size)
{
    const float* query = (const float*)d_in[0];
    const float* key   = (const float*)d_in[1];
    const float* value = (const float*)d_in[2];
    const int*   mask  = (const int*)  d_in[3];
    const float* abias = (const float*)d_in[4];
    const float* Wq = (const float*)d_in[5];
    const float* bq = (const float*)d_in[6];
    const float* Wk = (const float*)d_in[7];
    const float* bk = (const float*)d_in[8];
    const float* Wv = (const float*)d_in[9];
    const float* bv = (const float*)d_in[10];
    const float* Wo = (const float*)d_in[11];
    const float* bo = (const float*)d_in[12];
    float* out  = (float*)d_out;
    float* attn = out + OUT_ELEMS;

    cudaFuncSetAttribute(qkv_kernel,    cudaFuncAttributeMaxDynamicSharedMemorySize, PROJ_SMEM);
    cudaFuncSetAttribute(oproj_kernel,  cudaFuncAttributeMaxDynamicSharedMemorySize, PROJ_SMEM);
    cudaFuncSetAttribute(scores_kernel, cudaFuncAttributeMaxDynamicSharedMemorySize, SC_SMEM);
    cudaFuncSetAttribute(pv_kernel,     cudaFuncAttributeMaxDynamicSharedMemorySize, PV_SMEM);

    qkv_kernel<<<dim3(8,80), 256, PROJ_SMEM>>>(query, key, value, Wq, Wk, Wv, bq, bk, bv);

    scores_kernel<<<dim3(LK/128, LQ/128, BH), 256, SC_SMEM>>>(abias, mask, attn);
    merge_kernel<<<(BH*LQ)/256, 256>>>();
    pv_kernel<<<dim3(LQ/128, BH), 256, PV_SMEM>>>(attn);

    oproj_kernel<<<dim3(8,16), 256, PROJ_SMEM>>>(Wo, bo, out);
}

// round 13
// speedup vs baseline: 1.3552x; 1.3552x over previous
#include <cuda_runtime.h>
#include <cuda_bf16.h>
#include <cstdint>

#define B_  2
#define LQ  1024
#define LK  2048
#define DM  1024
#define NH  16
#define DH  64
#define BH  (B_*NH)
#define OUT_ELEMS (B_*LQ*DM)

// fp32 (tf32-rounded) pools
__device__ __align__(256) float  g_Q[BH*LQ*DH];     // scaled 1/8, rounded
__device__ __align__(256) float  g_K[BH*LK*DH];     // rounded
__device__ __align__(256) float  g_Vt[BH*DH*LK];    // [bh, d, t], rounded
__device__ __align__(256) float  g_ctx[B_*LQ*DM];
__device__ __align__(256) float2 g_pstats[BH*LQ*16];
__device__ __align__(256) float  g_scale[BH*LQ*16];

// ---------------- low-level helpers ----------------------------------------
__device__ __forceinline__ uint32_t smem_u32(const void* p){
    uint32_t a;
    asm("{ .reg .u64 t; cvta.to.shared.u64 t, %1; cvt.u32.u64 %0, t; }" : "=r"(a) : "l"(p));
    return a;
}
#define CP16(d,s) asm volatile("cp.async.cg.shared.global [%0], [%1], 16;" :: "r"(d), "l"(__cvta_generic_to_global(s)))
#define CPCOMMIT() asm volatile("cp.async.commit_group;" ::: "memory")
#define CPWAIT(n)  asm volatile("cp.async.wait_group %0;" :: "n"(n) : "memory")

__device__ __forceinline__ float tf32r(float x){
    uint32_t u; asm("cvt.rna.tf32.f32 %0, %1;" : "=r"(u) : "f"(x));
    return __uint_as_float(u);
}
__device__ __forceinline__ void mma_tf32(float* d, const float* a, const float* b){
    asm volatile("mma.sync.aligned.m16n8k8.row.col.f32.tf32.tf32.f32 "
        "{%0,%1,%2,%3}, {%4,%5,%6,%7}, {%8,%9}, {%0,%1,%2,%3};"
        : "+f"(d[0]),"+f"(d[1]),"+f"(d[2]),"+f"(d[3])
        : "r"(__float_as_uint(a[0])),"r"(__float_as_uint(a[1])),
          "r"(__float_as_uint(a[2])),"r"(__float_as_uint(a[3])),
          "r"(__float_as_uint(b[0])),"r"(__float_as_uint(b[1])));
}

// ============================================================================
// Projection: C[128x128] = A[M,1024] @ W[128,1024]^T + bias, tf32 MMA.
// 3-stage cp.async pipeline on raw fp32 tiles (k-chunks of 32); tf32 rounding
// happens in the fragment loads. smem = 512 + 6*18432 = 111104 -> 2 CTAs/SM.
// mode 0: Q (scale 1/8 -> g_Q), 1: K, 2: V transposed -> g_Vt, 3: O fp32 out
// ============================================================================
#define PTROW 36
#define PTILE (128*PTROW*4)            // 18432 B
#define PROJ_SMEM (512 + 6*PTILE)      // 111104 B

__device__ __forceinline__ void proj_issue(
    uint32_t sb, int tid, int ck, int m0, int n0,
    const float* __restrict__ A, const float* __restrict__ W)
{
    uint32_t base = sb + 512 + (uint32_t)(ck%3)*(2*PTILE);
#pragma unroll
    for (int i=0;i<4;i++){
        int idx = tid + i*256, row = idx>>3, c = idx&7;
        CP16(base + row*144 + c*16,         A + (size_t)(m0+row)*DM + ck*32 + c*4);
        CP16(base + PTILE + row*144 + c*16, W + (size_t)(n0+row)*DM + ck*32 + c*4);
    }
    CPCOMMIT();
}

__device__ __forceinline__ void proj_body(
    int mode, int m0, int n0,
    const float* __restrict__ A, const float* __restrict__ W,
    const float* __restrict__ bias, float* __restrict__ outp, int Ltok)
{
    extern __shared__ char smc[];
    const uint32_t sb = smem_u32(smc);
    float* bias_sm = (float*)smc;
    float* stg = (float*)(smc + 512);   // overlays tiles after final MMA

    const int tid = threadIdx.x, lane = tid&31, wid = tid>>5;
    const int wm = wid>>1, wn = wid&1;
    const int g = lane>>2, tg = lane&3;

    if (tid < 128) bias_sm[tid] = bias[n0+tid];

    float acc[2][8][4];
#pragma unroll
    for (int a=0;a<2;a++)
#pragma unroll
        for (int b=0;b<8;b++)
#pragma unroll
            for (int c=0;c<4;c++) acc[a][b][c]=0.f;

    proj_issue(sb, tid, 0, m0, n0, A, W);
    proj_issue(sb, tid, 1, m0, n0, A, W);

    for (int ck=0; ck<32; ck++){
        if (ck < 30){ proj_issue(sb, tid, ck+2, m0, n0, A, W); CPWAIT(2); }
        else if (ck == 30) CPWAIT(1);
        else CPWAIT(0);
        __syncthreads();

        const float* Sa = (const float*)(smc + 512 + (size_t)(ck%3)*(2*PTILE));
        const float* Sw = Sa + 128*PTROW;
#pragma unroll
        for (int ks=0;ks<4;ks++){
            float a[2][4];
#pragma unroll
            for (int mt=0;mt<2;mt++){
                int rb = wm*32 + mt*16;
                a[mt][0] = tf32r(Sa[(rb+g  )*PTROW + ks*8+tg]);
                a[mt][1] = tf32r(Sa[(rb+g+8)*PTROW + ks*8+tg]);
                a[mt][2] = tf32r(Sa[(rb+g  )*PTROW + ks*8+tg+4]);
                a[mt][3] = tf32r(Sa[(rb+g+8)*PTROW + ks*8+tg+4]);
            }
#pragma unroll
            for (int nt=0;nt<8;nt++){
                float b2[2];
                b2[0] = tf32r(Sw[(wn*64+nt*8+g)*PTROW + ks*8+tg]);
                b2[1] = tf32r(Sw[(wn*64+nt*8+g)*PTROW + ks*8+tg+4]);
                mma_tf32(acc[0][nt], a[0], b2);
                mma_tf32(acc[1][nt], a[1], b2);
            }
        }
        __syncthreads();
    }

    // stage accumulators (+bias, Q scale)
    {
#pragma unroll
        for (int mt=0;mt<2;mt++)
#pragma unroll
            for (int nt=0;nt<8;nt++){
                int row = wm*32 + mt*16 + g;
                int col = wn*64 + nt*8 + tg*2;
                float b0 = bias_sm[col], b1 = bias_sm[col+1];
                float v0 = acc[mt][nt][0]+b0, v1 = acc[mt][nt][1]+b1;
                float v2 = acc[mt][nt][2]+b0, v3 = acc[mt][nt][3]+b1;
                if (mode==0){ v0*=0.125f; v1*=0.125f; v2*=0.125f; v3*=0.125f; }
                stg[row*132+col] = v0;  stg[row*132+col+1] = v1;
                stg[(row+8)*132+col] = v2; stg[(row+8)*132+col+1] = v3;
            }
    }
    __syncthreads();

    if (mode==3){
        const int r2 = tid>>1, hf = tid&1;
        const float* srow = stg + r2*132 + hf*64;
        float* drow = outp + (size_t)(m0+r2)*DM + n0 + hf*64;
#pragma unroll
        for (int j=0;j<16;j++) *(float4*)(drow + j*4) = *(const float4*)(srow + j*4);
    } else if (mode<2){
        const int r2 = tid>>1, hf = tid&1;
        const int rowg = m0 + r2;
        const int b = rowg / Ltok, tok = rowg - b*Ltok;
        const int h = (n0>>6) + hf;
        const float* srow = stg + r2*132 + hf*64;
        float* dst = ((mode==0)? g_Q : g_K) + ((size_t)(b*NH+h)*Ltok + tok)*DH;
#pragma unroll
        for (int j=0;j<16;j++){
            float4 o;
            o.x=tf32r(srow[j*4+0]); o.y=tf32r(srow[j*4+1]);
            o.z=tf32r(srow[j*4+2]); o.w=tf32r(srow[j*4+3]);
            *(float4*)(dst + j*4) = o;
        }
    } else {
        const int dl = tid>>1, th = tid&1;
        const int dg = n0 + dl, h = dg>>6, dd = dg&63;
        const int b = m0 / Ltok, toff = m0 - b*Ltok;
        float* vt = g_Vt + ((size_t)(b*NH+h)*DH + dd)*LK + toff + th*64;
#pragma unroll
        for (int j=0;j<16;j++){
            int t4 = th*64 + j*4;
            float4 o;
            o.x=tf32r(stg[(t4+0)*132+dl]);
            o.y=tf32r(stg[(t4+1)*132+dl]);
            o.z=tf32r(stg[(t4+2)*132+dl]);
            o.w=tf32r(stg[(t4+3)*132+dl]);
            *(float4*)(vt + j*4) = o;
        }
    }
}

// fused Q/K/V projection: grid (8, 80): y<16 Q, y<48 K, else V
__global__ void __launch_bounds__(256,2) qkv_kernel(
    const float* __restrict__ query, const float* __restrict__ key, const float* __restrict__ value,
    const float* __restrict__ Wq, const float* __restrict__ Wk, const float* __restrict__ Wv,
    const float* __restrict__ bq, const float* __restrict__ bk, const float* __restrict__ bv)
{
    const int my = blockIdx.y, n0 = blockIdx.x*128;
    if (my < 16)
        proj_body(0, my*128, n0, query, Wq, bq, nullptr, LQ);
    else if (my < 48)
        proj_body(1, (my-16)*128, n0, key, Wk, bk, nullptr, LK);
    else
        proj_body(2, (my-48)*128, n0, value, Wv, bv, nullptr, LK);
}

__global__ void __launch_bounds__(256,2) oproj_kernel(
    const float* __restrict__ Wo, const float* __restrict__ bo, float* __restrict__ out)
{
    proj_body(3, blockIdx.y*128, blockIdx.x*128, g_ctx, Wo, bo, out, LQ);
}

// ============================================================================
// Scores (unchanged from R12): S = Q@K^T + bias, mask; writes exp(s-m_tile)
// to attn, per-tile (max,sum) -> g_pstats.
// ============================================================================
#define TROW   68
#define TILEB  (128*TROW*4)     // 34816 bytes
#define SC_SMEM (2*TILEB)
__global__ void __launch_bounds__(256,2) scores_kernel(
    const float* __restrict__ bias, const int* __restrict__ mask,
    float* __restrict__ attn)
{
    extern __shared__ char smc[];
    const uint32_t sb = smem_u32(smc);
    float* Sq = (float*)smc;
    float* Sk = Sq + 128*TROW;
    float* stg = (float*)smc;
    const int tid = threadIdx.x, lane = tid&31, wid = tid>>5;
    const int wm = wid>>1, wn = wid&1;
    const int g = lane>>2, tg = lane&3;
    const int k0 = blockIdx.x*128, q0 = blockIdx.y*128, bh = blockIdx.z, b = bh>>4;
    const int kt = blockIdx.x;

    const float* Qg = g_Q + ((size_t)bh*LQ + q0)*DH;
    const float* Kg = g_K + ((size_t)bh*LK + k0)*DH;
#pragma unroll
    for (int i=0;i<8;i++){
        int idx = tid + i*256, row = idx>>4, c = idx&15;
        CP16(sb + row*(TROW*4) + c*16,         Qg + (size_t)row*DH + c*4);
        CP16(sb + TILEB + row*(TROW*4) + c*16, Kg + (size_t)row*DH + c*4);
    }
    CPCOMMIT(); CPWAIT(0);
    __syncthreads();

    float acc[2][8][4];
#pragma unroll
    for (int a=0;a<2;a++)
#pragma unroll
        for (int c=0;c<8;c++)
#pragma unroll
            for (int d=0;d<4;d++) acc[a][c][d]=0.f;

#pragma unroll
    for (int ks=0;ks<8;ks++){
        float a[2][4];
#pragma unroll
        for (int mt=0;mt<2;mt++){
            int rb = wm*32 + mt*16;
            a[mt][0] = Sq[(rb+g  )*TROW + ks*8+tg];
            a[mt][1] = Sq[(rb+g+8)*TROW + ks*8+tg];
            a[mt][2] = Sq[(rb+g  )*TROW + ks*8+tg+4];
            a[mt][3] = Sq[(rb+g+8)*TROW + ks*8+tg+4];
        }
#pragma unroll
        for (int nt=0;nt<8;nt++){
            float b2[2];
            b2[0] = Sk[(wn*64+nt*8+g)*TROW + ks*8+tg];
            b2[1] = Sk[(wn*64+nt*8+g)*TROW + ks*8+tg+4];
            mma_tf32(acc[0][nt], a[0], b2);
            mma_tf32(acc[1][nt], a[1], b2);
        }
    }
    __syncthreads();   // tiles dead; stage overlays
    {
#pragma unroll
        for (int mt=0;mt<2;mt++)
#pragma unroll
            for (int nt=0;nt<8;nt++){
                int row = wm*32 + mt*16 + g;
                int col = wn*64 + nt*8 + tg*2;
                stg[row*132+col] = acc[mt][nt][0];  stg[row*132+col+1] = acc[mt][nt][1];
                stg[(row+8)*132+col] = acc[mt][nt][2]; stg[(row+8)*132+col+1] = acc[mt][nt][3];
            }
    }
    __syncthreads();
    {
        const int r2 = tid>>1, hf = tid&1;
        const int q = q0 + r2;
        float* srow = stg + r2*132 + hf*64;
        const float* brow = bias + ((size_t)bh*LQ + q)*LK + k0 + hf*64;
        const int*   mrow = mask + ((size_t)b*LQ  + q)*LK + k0 + hf*64;
        float mx = -3.0e38f;
#pragma unroll
        for (int j=0;j<16;j++){
            float4 s = *(const float4*)(srow + j*4);
            float4 bb = *(const float4*)(brow + j*4);
            int4   mm = *(const int4*)  (mrow + j*4);
            s.x = mm.x ? s.x+bb.x : -1e9f;
            s.y = mm.y ? s.y+bb.y : -1e9f;
            s.z = mm.z ? s.z+bb.z : -1e9f;
            s.w = mm.w ? s.w+bb.w : -1e9f;
            mx = fmaxf(mx, fmaxf(fmaxf(s.x,s.y), fmaxf(s.z,s.w)));
            *(float4*)(srow + j*4) = s;
        }
        mx = fmaxf(mx, __shfl_xor_sync(0xffffffffu, mx, 1));
        float sum = 0.f;
        float* arow = attn + ((size_t)bh*LQ + q)*LK + k0 + hf*64;
#pragma unroll
        for (int j=0;j<16;j++){
            float4 s = *(const float4*)(srow + j*4);
            float4 e;
            e.x = __expf(s.x-mx); e.y = __expf(s.y-mx);
            e.z = __expf(s.z-mx); e.w = __expf(s.w-mx);
            sum += (e.x+e.y)+(e.z+e.w);
            *(float4*)(arow + j*4) = e;
        }
        sum += __shfl_xor_sync(0xffffffffu, sum, 1);
        if (hf == 0)
            g_pstats[((size_t)bh*LQ + q)*16 + kt] = make_float2(mx, sum);
    }
}

// ============================================================================
// Merge per-row tile partials -> per-tile normalization scales
// ============================================================================
__global__ void __launch_bounds__(256) merge_kernel()
{
    const int row = blockIdx.x*256 + threadIdx.x;
    float2 p[16];
#pragma unroll
    for (int t=0;t<16;t++) p[t] = g_pstats[(size_t)row*16 + t];
    float m = p[0].x;
#pragma unroll
    for (int t=1;t<16;t++) m = fmaxf(m, p[t].x);
    float e[16]; float S = 0.f;
#pragma unroll
    for (int t=0;t<16;t++){ e[t] = __expf(p[t].x - m); S += p[t].y * e[t]; }
    const float inv = 1.f / S;
#pragma unroll
    for (int t=0;t<16;t++) g_scale[(size_t)row*16 + t] = e[t] * inv;
}

// ============================================================================
// PV: double-buffered cp.async on raw exp P + V. Scale+round folded into the
// fragment loads; normalized attn writeback from smem.
// smem: P0@0 P1@34816 | V0@69632 V1@87040 (64x68f each) | ssc@104448 (8KB)
// Total 112640 -> 2 CTAs/SM. Epilogue stage overlays P0.
// ============================================================================
#define PV_VOFF 69632
#define PV_SOFF 104448
#define PV_SMEM (PV_SOFF + 8192)

__device__ __forceinline__ void pv_issue(
    uint32_t sb, int tid, int ck,
    const float* __restrict__ Pg, const float* __restrict__ Vg)
{
    uint32_t pb = sb + (uint32_t)(ck&1)*TILEB;
    uint32_t vb = sb + PV_VOFF + (uint32_t)(ck&1)*17408;
#pragma unroll
    for (int i=0;i<8;i++){
        int idx = tid + i*256, row = idx>>4, c = idx&15;
        CP16(pb + row*(TROW*4) + c*16, Pg + (size_t)row*LK + ck*64 + c*4);
    }
#pragma unroll
    for (int i=0;i<4;i++){
        int idx = tid + i*256, row = idx>>4, c = idx&15;
        CP16(vb + row*(TROW*4) + c*16, Vg + (size_t)row*LK + ck*64 + c*4);
    }
    CPCOMMIT();
}

__global__ void __launch_bounds__(256,2) pv_kernel(float* __restrict__ attn)
{
    extern __shared__ char smc[];
    const uint32_t sb = smem_u32(smc);
    float* ssc = (float*)(smc + PV_SOFF);
    float* stg = (float*)smc;                // overlays P0 at the end
    const int tid = threadIdx.x, lane = tid&31, wid = tid>>5;
    const int wm = wid>>1, wn = wid&1;
    const int g = lane>>2, tg = lane&3;
    const int q0 = blockIdx.x*128, bh = blockIdx.y, b = bh>>4, h = bh&15;

    float* Pg = attn + ((size_t)bh*LQ + q0)*LK;
    const float* Vg = g_Vt + (size_t)bh*DH*LK;

#pragma unroll
    for (int i=0;i<8;i++){
        int idx = tid + i*256;
        int r = idx>>4;
        ssc[idx] = g_scale[((size_t)bh*LQ + q0 + r)*16 + (idx&15)];
    }

    float acc[2][4][4];
#pragma unroll
    for (int a=0;a<2;a++)
#pragma unroll
        for (int c=0;c<4;c++)
#pragma unroll
            for (int d=0;d<4;d++) acc[a][c][d]=0.f;

    pv_issue(sb, tid, 0, Pg, Vg);

    for (int ck=0; ck<32; ck++){
        if (ck < 31){ pv_issue(sb, tid, ck+1, Pg, Vg); CPWAIT(1); }
        else CPWAIT(0);
        __syncthreads();

        const float* Pb = (const float*)(smc + (size_t)(ck&1)*TILEB);
        const float* Vb = (const float*)(smc + PV_VOFF + (size_t)(ck&1)*17408);
        const int kt2 = ck>>1;

        // normalized attn writeback (from smem; stores fire-and-forget)
#pragma unroll
        for (int i=0;i<8;i++){
            int idx = tid + i*256, row = idx>>4, c4 = idx&15;
            const float sc = ssc[row*16 + kt2];
            float4 v = *(const float4*)(Pb + row*TROW + c4*4);
            v.x *= sc; v.y *= sc; v.z *= sc; v.w *= sc;
            *(float4*)(Pg + (size_t)row*LK + ck*64 + c4*4) = v;
        }

        // MMA with scale+round folded into A-fragment loads
#pragma unroll
        for (int mt=0;mt<2;mt++){
            const int r0 = wm*32 + mt*16 + g;
            const float s0 = ssc[r0*16 + kt2];
            const float s1 = ssc[(r0+8)*16 + kt2];
#pragma unroll
            for (int ks=0;ks<8;ks++){
                float a[4];
                a[0] = tf32r(Pb[r0    *TROW + ks*8+tg  ] * s0);
                a[1] = tf32r(Pb[(r0+8)*TROW + ks*8+tg  ] * s1);
                a[2] = tf32r(Pb[r0    *TROW + ks*8+tg+4] * s0);
                a[3] = tf32r(Pb[(r0+8)*TROW + ks*8+tg+4] * s1);
#pragma unroll
                for (int nt=0;nt<4;nt++){
                    float b2[2];
                    b2[0] = Vb[(wn*32+nt*8+g)*TROW + ks*8+tg];
                    b2[1] = Vb[(wn*32+nt*8+g)*TROW + ks*8+tg+4];
                    mma_tf32(acc[mt][nt], a, b2);
                }
            }
        }
        __syncthreads();
    }

    // epilogue: stage + coalesced ctx store
    {
#pragma unroll
        for (int mt=0;mt<2;mt++)
#pragma unroll
            for (int nt=0;nt<4;nt++){
                int row = wm*32 + mt*16 + g;
                int col = wn*32 + nt*8 + tg*2;
                stg[row*TROW+col] = acc[mt][nt][0];  stg[row*TROW+col+1] = acc[mt][nt][1];
                stg[(row+8)*TROW+col] = acc[mt][nt][2]; stg[(row+8)*TROW+col+1] = acc[mt][nt][3];
            }
    }
    __syncthreads();
    {
        const int r2 = tid>>1, hf = tid&1;
        const float* srow = stg + r2*TROW + hf*32;
        float* dst = g_ctx + ((size_t)(b*LQ + q0 + r2))*DM + h*DH + hf*32;
#pragma unroll
        for (int j=0;j<8;j++){
            float4 o;
            o.x=tf32r(srow[j*4+0]); o.y=tf32r(srow[j*4+1]);
            o.z=tf32r(srow[j*4+2]); o.w=tf32r(srow[j*4+3]);
            *(float4*)(dst + j*4) = o;
        }
    }
}

// ============================================================================
extern "C" void kernel_launch(void* const* d_in, const int* in_sizes, int n_in,
                              void* d_out, int out_size)
{
    const float* query = (const float*)d_in[0];
    const float* key   = (const float*)d_in[1];
    const float* value = (const float*)d_in[2];
    const int*   mask  = (const int*)  d_in[3];
    const float* abias = (const float*)d_in[4];
    const float* Wq = (const float*)d_in[5];
    const float* bq = (const float*)d_in[6];
    const float* Wk = (const float*)d_in[7];
    const float* bk = (const float*)d_in[8];
    const float* Wv = (const float*)d_in[9];
    const float* bv = (const float*)d_in[10];
    const float* Wo = (const float*)d_in[11];
    const float* bo = (const float*)d_in[12];
    float* out  = (float*)d_out;
    float* attn = out + OUT_ELEMS;

    cudaFuncSetAttribute(qkv_kernel,    cudaFuncAttributeMaxDynamicSharedMemorySize, PROJ_SMEM);
    cudaFuncSetAttribute(oproj_kernel,  cudaFuncAttributeMaxDynamicSharedMemorySize, PROJ_SMEM);
    cudaFuncSetAttribute(scores_kernel, cudaFuncAttributeMaxDynamicSharedMemorySize, SC_SMEM);
    cudaFuncSetAttribute(pv_kernel,     cudaFuncAttributeMaxDynamicSharedMemorySize, PV_SMEM);

    qkv_kernel<<<dim3(8,80), 256, PROJ_SMEM>>>(query, key, value, Wq, Wk, Wv, bq, bk, bv);

    scores_kernel<<<dim3(LK/128, LQ/128, BH), 256, SC_SMEM>>>(abias, mask, attn);
    merge_kernel<<<(BH*LQ)/256, 256>>>();
    pv_kernel<<<dim3(LQ/128, BH), 256, PV_SMEM>>>(attn);

    oproj_kernel<<<dim3(8,16), 256, PROJ_SMEM>>>(Wo, bo, out);
}